// round 2
// baseline (speedup 1.0000x reference)
#include <cuda_runtime.h>
#include <math.h>

#define Cdim   512
#define Tdim   8
#define HWdim  2304            // H*W = 48*48
#define Ndim   18432           // T*H*W
#define Gdim   32
#define CPG    16              // channels per group
#define EPSv   1e-6f
#define SCALEv 0.044194173824159216f   // 512^-0.5

// ---------------- scratch (__device__ globals: allocation-free) ----------------
__device__ float g_mean[Gdim];
__device__ float g_rstd[Gdim];
__device__ float g_hn[(size_t)Cdim * Ndim];
__device__ float g_q [(size_t)Cdim * Ndim];
__device__ float g_k [(size_t)Cdim * Ndim];
__device__ float g_v [(size_t)Cdim * Ndim];
__device__ float g_of[(size_t)Cdim * Ndim];
__device__ float g_s [(size_t)Tdim * HWdim * HWdim];   // attention scores / probs

// ---------------- GroupNorm statistics: one block per group ----------------
__global__ void gn_stats_kernel(const float* __restrict__ x) {
    const int g = blockIdx.x;
    const float4* base = (const float4*)(x + (size_t)g * CPG * Ndim);
    const int n4 = (CPG * Ndim) / 4;     // 73728
    float s = 0.f, ss = 0.f;
    for (int i = threadIdx.x; i < n4; i += blockDim.x) {
        float4 v = base[i];
        s  += v.x + v.y + v.z + v.w;
        ss += v.x*v.x + v.y*v.y + v.z*v.z + v.w*v.w;
    }
    __shared__ float sh1[1024];
    __shared__ float sh2[1024];
    sh1[threadIdx.x] = s;
    sh2[threadIdx.x] = ss;
    __syncthreads();
    for (int off = 512; off > 0; off >>= 1) {
        if (threadIdx.x < off) {
            sh1[threadIdx.x] += sh1[threadIdx.x + off];
            sh2[threadIdx.x] += sh2[threadIdx.x + off];
        }
        __syncthreads();
    }
    if (threadIdx.x == 0) {
        const float inv = 1.f / (float)(CPG * Ndim);
        float m   = sh1[0] * inv;
        float var = sh2[0] * inv - m * m;
        g_mean[g] = m;
        g_rstd[g] = rsqrtf(var + EPSv);
    }
}

// ---------------- GroupNorm apply: hn = (x-mu)*rstd*gamma + beta ----------------
__global__ void gn_apply_kernel(const float* __restrict__ x,
                                const float* __restrict__ gamma,
                                const float* __restrict__ beta) {
    int i4 = blockIdx.x * blockDim.x + threadIdx.x;    // float4 index
    int c  = (i4 * 4) / Ndim;                          // Ndim % 4 == 0 -> same c for all lanes
    int g  = c >> 4;
    float r  = g_rstd[g];
    float ga = gamma[c] * r;
    float be = beta[c] - g_mean[g] * ga;
    float4 v = ((const float4*)x)[i4];
    v.x = v.x * ga + be;
    v.y = v.y * ga + be;
    v.z = v.z * ga + be;
    v.w = v.w * ga + be;
    ((float4*)g_hn)[i4] = v;
}

// ---------------- NN sgemm: C[m][n] = sum_k A[m][k]*B[k][n] + bias[m] (+resid) ----------------
// A: MxK row-major (weights), B: KxN row-major. 128x128x8 tiles, 8x8 per thread.
__global__ void __launch_bounds__(256)
sgemm_nn_kernel(const float* __restrict__ A, const float* __restrict__ B,
                const float* __restrict__ bias, const float* __restrict__ resid,
                float* __restrict__ Cmat, int M, int N, int K) {
    __shared__ float As[8][128];
    __shared__ float Bs[8][128];
    const int tid = threadIdx.x;
    const int bm = blockIdx.y * 128, bn = blockIdx.x * 128;
    const int tx = tid & 15, ty = tid >> 4;
    const int arow = tid >> 1, acol = (tid & 1) * 4;    // A: 128 rows x 8 k
    const int brow = tid >> 5, bcol = (tid & 31) * 4;   // B: 8 k x 128 cols
    float acc[8][8] = {};
    const float* Ap = A + (size_t)(bm + arow) * K + acol;
    const float* Bp = B + (size_t)brow * N + bn + bcol;
    for (int k0 = 0; k0 < K; k0 += 8) {
        float4 a4 = *(const float4*)(Ap + k0);
        As[acol + 0][arow] = a4.x;
        As[acol + 1][arow] = a4.y;
        As[acol + 2][arow] = a4.z;
        As[acol + 3][arow] = a4.w;
        *(float4*)&Bs[brow][bcol] = *(const float4*)(Bp + (size_t)k0 * N);
        __syncthreads();
#pragma unroll
        for (int kk = 0; kk < 8; kk++) {
            float ar[8], br[8];
            *(float4*)(ar)     = *(const float4*)&As[kk][ty * 8];
            *(float4*)(ar + 4) = *(const float4*)&As[kk][ty * 8 + 4];
            *(float4*)(br)     = *(const float4*)&Bs[kk][tx * 8];
            *(float4*)(br + 4) = *(const float4*)&Bs[kk][tx * 8 + 4];
#pragma unroll
            for (int i = 0; i < 8; i++)
#pragma unroll
                for (int j = 0; j < 8; j++)
                    acc[i][j] = fmaf(ar[i], br[j], acc[i][j]);
        }
        __syncthreads();
    }
#pragma unroll
    for (int i = 0; i < 8; i++) {
        const int m = bm + ty * 8 + i;
        const float bi = bias[m];
        float* crow = Cmat + (size_t)m * N + bn + tx * 8;
        const float* rrow = resid ? (resid + (size_t)m * N + bn + tx * 8) : (const float*)0;
#pragma unroll
        for (int j = 0; j < 8; j += 4) {
            float4 v;
            v.x = acc[i][j + 0] + bi;
            v.y = acc[i][j + 1] + bi;
            v.z = acc[i][j + 2] + bi;
            v.w = acc[i][j + 3] + bi;
            if (rrow) {
                float4 r = *(const float4*)(rrow + j);
                v.x += r.x; v.y += r.y; v.z += r.z; v.w += r.w;
            }
            *(float4*)(crow + j) = v;
        }
    }
}

// ---------------- scores (TN): S[i][j] = scale * sum_c Q[c][i]*K[c][j], per frame ----------------
__global__ void __launch_bounds__(256)
scores_kernel() {
    const int f = blockIdx.z;
    const float* Q  = g_q + (size_t)f * HWdim;
    const float* Kp = g_k + (size_t)f * HWdim;
    float* S = g_s + (size_t)f * HWdim * HWdim;
    __shared__ float As[8][128];
    __shared__ float Bs[8][128];
    const int tid = threadIdx.x;
    const int bm = blockIdx.y * 128, bn = blockIdx.x * 128;
    const int tx = tid & 15, ty = tid >> 4;
    const int lr = tid >> 5, lc = (tid & 31) * 4;      // 8 k rows x 128 cols, direct copy
    float acc[8][8] = {};
    for (int k0 = 0; k0 < Cdim; k0 += 8) {
        *(float4*)&As[lr][lc] = *(const float4*)(Q  + (size_t)(k0 + lr) * Ndim + bm + lc);
        *(float4*)&Bs[lr][lc] = *(const float4*)(Kp + (size_t)(k0 + lr) * Ndim + bn + lc);
        __syncthreads();
#pragma unroll
        for (int kk = 0; kk < 8; kk++) {
            float ar[8], br[8];
            *(float4*)(ar)     = *(const float4*)&As[kk][ty * 8];
            *(float4*)(ar + 4) = *(const float4*)&As[kk][ty * 8 + 4];
            *(float4*)(br)     = *(const float4*)&Bs[kk][tx * 8];
            *(float4*)(br + 4) = *(const float4*)&Bs[kk][tx * 8 + 4];
#pragma unroll
            for (int i = 0; i < 8; i++)
#pragma unroll
                for (int j = 0; j < 8; j++)
                    acc[i][j] = fmaf(ar[i], br[j], acc[i][j]);
        }
        __syncthreads();
    }
#pragma unroll
    for (int i = 0; i < 8; i++) {
        float* row = S + (size_t)(bm + ty * 8 + i) * HWdim + bn + tx * 8;
#pragma unroll
        for (int j = 0; j < 8; j += 4) {
            float4 v;
            v.x = acc[i][j + 0] * SCALEv;
            v.y = acc[i][j + 1] * SCALEv;
            v.z = acc[i][j + 2] * SCALEv;
            v.w = acc[i][j + 3] * SCALEv;
            *(float4*)(row + j) = v;
        }
    }
}

// ---------------- row softmax over 2304 cols (register-resident, 1 RD + 1 WR) ----------------
__global__ void __launch_bounds__(256)
softmax_kernel() {
    float* row = g_s + (size_t)blockIdx.x * HWdim;
    const int tid = threadIdx.x;
    float r[9];
    float mx = -1e30f;
#pragma unroll
    for (int i = 0; i < 9; i++) {
        r[i] = row[tid + i * 256];
        mx = fmaxf(mx, r[i]);
    }
    __shared__ float sh[256];
    sh[tid] = mx;
    __syncthreads();
    for (int off = 128; off > 0; off >>= 1) {
        if (tid < off) sh[tid] = fmaxf(sh[tid], sh[tid + off]);
        __syncthreads();
    }
    mx = sh[0];
    __syncthreads();
    float s = 0.f;
#pragma unroll
    for (int i = 0; i < 9; i++) {
        r[i] = __expf(r[i] - mx);
        s += r[i];
    }
    sh[tid] = s;
    __syncthreads();
    for (int off = 128; off > 0; off >>= 1) {
        if (tid < off) sh[tid] += sh[tid + off];
        __syncthreads();
    }
    const float inv = 1.f / sh[0];
#pragma unroll
    for (int i = 0; i < 9; i++) row[tid + i * 256] = r[i] * inv;
}

// ---------------- PV (NT): O[c][i] = sum_j V[c][j] * P[i][j], per frame ----------------
__global__ void __launch_bounds__(256)
pv_kernel() {
    const int f = blockIdx.z;
    const float* V = g_v + (size_t)f * HWdim;                 // [C][Ndim], frame col offset
    const float* S = g_s + (size_t)f * HWdim * HWdim;          // [i][j]
    float* O = g_of + (size_t)f * HWdim;
    __shared__ float As[8][128];
    __shared__ float Bs[8][128];
    const int tid = threadIdx.x;
    const int bm = blockIdx.y * 128, bn = blockIdx.x * 128;    // bm: c, bn: i
    const int tx = tid & 15, ty = tid >> 4;
    const int arow = tid >> 1, acol = (tid & 1) * 4;           // 128 rows x 8 k, transpose-store
    float acc[8][8] = {};
    for (int k0 = 0; k0 < HWdim; k0 += 8) {
        float4 a4 = *(const float4*)(V + (size_t)(bm + arow) * Ndim + k0 + acol);
        As[acol + 0][arow] = a4.x;
        As[acol + 1][arow] = a4.y;
        As[acol + 2][arow] = a4.z;
        As[acol + 3][arow] = a4.w;
        float4 b4 = *(const float4*)(S + (size_t)(bn + arow) * HWdim + k0 + acol);
        Bs[acol + 0][arow] = b4.x;
        Bs[acol + 1][arow] = b4.y;
        Bs[acol + 2][arow] = b4.z;
        Bs[acol + 3][arow] = b4.w;
        __syncthreads();
#pragma unroll
        for (int kk = 0; kk < 8; kk++) {
            float ar[8], br[8];
            *(float4*)(ar)     = *(const float4*)&As[kk][ty * 8];
            *(float4*)(ar + 4) = *(const float4*)&As[kk][ty * 8 + 4];
            *(float4*)(br)     = *(const float4*)&Bs[kk][tx * 8];
            *(float4*)(br + 4) = *(const float4*)&Bs[kk][tx * 8 + 4];
#pragma unroll
            for (int i = 0; i < 8; i++)
#pragma unroll
                for (int j = 0; j < 8; j++)
                    acc[i][j] = fmaf(ar[i], br[j], acc[i][j]);
        }
        __syncthreads();
    }
#pragma unroll
    for (int i = 0; i < 8; i++) {
        float* crow = O + (size_t)(bm + ty * 8 + i) * Ndim + bn + tx * 8;
#pragma unroll
        for (int j = 0; j < 8; j += 4) {
            float4 v;
            v.x = acc[i][j + 0];
            v.y = acc[i][j + 1];
            v.z = acc[i][j + 2];
            v.w = acc[i][j + 3];
            *(float4*)(crow + j) = v;
        }
    }
}

// ---------------- launch ----------------
extern "C" void kernel_launch(void* const* d_in, const int* in_sizes, int n_in,
                              void* d_out, int out_size) {
    // device addresses of scratch first (host API, not stream-ordered, capture-safe)
    float *p_hn, *p_q, *p_k, *p_v, *p_of;
    cudaGetSymbolAddress((void**)&p_hn, g_hn);
    cudaGetSymbolAddress((void**)&p_q,  g_q);
    cudaGetSymbolAddress((void**)&p_k,  g_k);
    cudaGetSymbolAddress((void**)&p_v,  g_v);
    cudaGetSymbolAddress((void**)&p_of, g_of);

    const float* x     = (const float*)d_in[0];
    const float* gamma = (const float*)d_in[1];
    const float* beta  = (const float*)d_in[2];
    const float* wq    = (const float*)d_in[3];
    const float* bq    = (const float*)d_in[4];
    const float* wk    = (const float*)d_in[5];
    const float* bk    = (const float*)d_in[6];
    const float* wv    = (const float*)d_in[7];
    const float* bv    = (const float*)d_in[8];
    const float* wo    = (const float*)d_in[9];
    const float* bo    = (const float*)d_in[10];
    float* out = (float*)d_out;

    // 1. GroupNorm
    gn_stats_kernel<<<Gdim, 1024>>>(x);
    gn_apply_kernel<<<(Cdim * Ndim / 4) / 256, 256>>>(x, gamma, beta);

    // 2. Q/K/V projections: 512x18432 = Wq(512x512) @ hn(512x18432)
    dim3 gProj(Ndim / 128, Cdim / 128);   // (144, 4)
    sgemm_nn_kernel<<<gProj, 256>>>(wq, p_hn, bq, (const float*)0, p_q, Cdim, Ndim, Cdim);
    sgemm_nn_kernel<<<gProj, 256>>>(wk, p_hn, bk, (const float*)0, p_k, Cdim, Ndim, Cdim);
    sgemm_nn_kernel<<<gProj, 256>>>(wv, p_hn, bv, (const float*)0, p_v, Cdim, Ndim, Cdim);

    // 3. scores = scale * Q^T K per frame
    dim3 gSc(HWdim / 128, HWdim / 128, Tdim);   // (18, 18, 8)
    scores_kernel<<<gSc, 256>>>();

    // 4. softmax over rows
    softmax_kernel<<<Tdim * HWdim, 256>>>();

    // 5. O = V @ P^T per frame
    dim3 gPV(HWdim / 128, Cdim / 128, Tdim);    // (18, 4, 8)
    pv_kernel<<<gPV, 256>>>();

    // 6. output projection + bias + residual -> d_out
    sgemm_nn_kernel<<<gProj, 256>>>(wo, p_of, bo, x, out, Cdim, Ndim, Cdim);
}

// round 5
// speedup vs baseline: 1.5982x; 1.5982x over previous
#include <cuda_runtime.h>
#include <cuda_bf16.h>
#include <stdint.h>
#include <math.h>

#define Cdim   512
#define Tdim   8
#define HWdim  2304            // H*W
#define Ndim   18432           // T*H*W
#define Gdim   32
#define CPG    16
#define EPSv   1e-6f
#define SCALEv 0.044194173824159216f   // 512^-0.5

// ---------------- scratch ----------------
__device__ float g_mean[Gdim];
__device__ float g_rstd[Gdim];
__device__ float g_hn[(size_t)Cdim * Ndim];
__device__ float g_q [(size_t)Cdim * Ndim];
__device__ float g_k [(size_t)Cdim * Ndim];
__device__ float g_v [(size_t)Cdim * Ndim];
__device__ float g_of[(size_t)Cdim * Ndim];
__device__ float g_s [(size_t)Tdim * HWdim * HWdim];

// ---------------- GroupNorm ----------------
__global__ void gn_stats_kernel(const float* __restrict__ x) {
    const int g = blockIdx.x;
    const float4* base = (const float4*)(x + (size_t)g * CPG * Ndim);
    const int n4 = (CPG * Ndim) / 4;
    float s = 0.f, ss = 0.f;
    for (int i = threadIdx.x; i < n4; i += blockDim.x) {
        float4 v = base[i];
        s  += v.x + v.y + v.z + v.w;
        ss += v.x*v.x + v.y*v.y + v.z*v.z + v.w*v.w;
    }
    __shared__ float sh1[1024];
    __shared__ float sh2[1024];
    sh1[threadIdx.x] = s; sh2[threadIdx.x] = ss;
    __syncthreads();
    for (int off = 512; off > 0; off >>= 1) {
        if (threadIdx.x < off) {
            sh1[threadIdx.x] += sh1[threadIdx.x + off];
            sh2[threadIdx.x] += sh2[threadIdx.x + off];
        }
        __syncthreads();
    }
    if (threadIdx.x == 0) {
        const float inv = 1.f / (float)(CPG * Ndim);
        float m = sh1[0] * inv;
        float var = sh2[0] * inv - m * m;
        g_mean[g] = m;
        g_rstd[g] = rsqrtf(var + EPSv);
    }
}

__global__ void gn_apply_kernel(const float* __restrict__ x,
                                const float* __restrict__ gamma,
                                const float* __restrict__ beta) {
    int i4 = blockIdx.x * blockDim.x + threadIdx.x;
    int c  = (i4 * 4) / Ndim;
    int g  = c >> 4;
    float r  = g_rstd[g];
    float ga = gamma[c] * r;
    float be = beta[c] - g_mean[g] * ga;
    float4 v = ((const float4*)x)[i4];
    v.x = v.x * ga + be; v.y = v.y * ga + be;
    v.z = v.z * ga + be; v.w = v.w * ga + be;
    ((float4*)g_hn)[i4] = v;
}

// ---------------- tensor-core GEMM (bf16x3 split for fp32 accuracy) ----------------
__device__ __forceinline__ uint32_t smem_u32(const void* p) {
    return (uint32_t)__cvta_generic_to_shared(p);
}

#define LDMX4(r0,r1,r2,r3,addr) \
    asm volatile("ldmatrix.sync.aligned.m8n8.x4.shared.b16 {%0,%1,%2,%3}, [%4];" \
        : "=r"(r0),"=r"(r1),"=r"(r2),"=r"(r3) : "r"(addr))
#define LDMX2T(r0,r1,addr) \
    asm volatile("ldmatrix.sync.aligned.m8n8.x2.trans.shared.b16 {%0,%1}, [%2];" \
        : "=r"(r0),"=r"(r1) : "r"(addr))
#define MMA_B16(c0,c1,c2,c3,a0,a1,a2,a3,b0,b1) \
    asm volatile("mma.sync.aligned.m16n8k16.row.col.f32.bf16.bf16.f32 " \
        "{%0,%1,%2,%3}, {%4,%5,%6,%7}, {%8,%9}, {%0,%1,%2,%3};" \
        : "+f"(c0),"+f"(c1),"+f"(c2),"+f"(c3) \
        : "r"(a0),"r"(a1),"r"(a2),"r"(a3),"r"(b0),"r"(b1))

__device__ __forceinline__ void split_bf16(float x, __nv_bfloat16& h, __nv_bfloat16& l) {
    h = __float2bfloat16(x);
    l = __float2bfloat16(x - __bfloat162float(h));
}

// MODE 0: proj   C[M=512][N=18432] = A[512][512] @ B[512][18432] (+bias, +resid)
// MODE 1: scores S_f[2304][2304] = scale * Q_f^T K_f  (A transposed-load from g_q)
// MODE 2: pv     O_f[512][2304]  = V_f @ P_f^T        (B transposed-load from g_s)
template<int MODE>
__global__ void __launch_bounds__(256)
mma_gemm(const float* __restrict__ Ag, const float* __restrict__ Bg,
         const float* __restrict__ bias, const float* __restrict__ resid,
         float* __restrict__ Cg)
{
    constexpr int KDIM = (MODE == 2) ? HWdim : Cdim;
    constexpr int NSTG = KDIM / 32;

    __shared__ __align__(16) __nv_bfloat16 Ah[128][40];
    __shared__ __align__(16) __nv_bfloat16 Al[128][40];
    __shared__ __align__(16) __nv_bfloat16 Bh[32][136];
    __shared__ __align__(16) __nv_bfloat16 Bl[32][136];

    const int tid  = threadIdx.x;
    const int lane = tid & 31;
    const int warp = tid >> 5;
    const int wm   = (warp >> 2) * 64;
    const int wn   = (warp & 3) * 32;
    const int bn   = blockIdx.x * 128;
    const int bm   = blockIdx.y * 128;
    const int f    = (MODE == 0) ? 0 : blockIdx.z;

    const float* Ap;
    const float* Bp;
    float* Cp;
    if (MODE == 0) { Ap = Ag; Bp = Bg; Cp = Cg; }
    else if (MODE == 1) {
        Ap = Ag + (size_t)f * HWdim;                  // Q: [k][m] strided Ndim
        Bp = Bg + (size_t)f * HWdim;                  // K: [k][n] strided Ndim
        Cp = Cg + (size_t)f * HWdim * HWdim;
    } else {
        Ap = Ag + (size_t)f * HWdim;                  // V: [m][k] strided Ndim
        Bp = Bg + (size_t)f * HWdim * HWdim;          // P: [n][k] strided HWdim
        Cp = Cg + (size_t)f * HWdim;
    }

    float4 pa[4], pb[4];

    // ---- load stage k0 into registers ----
    auto loadA = [&](int k0, float4* r) {
        if (MODE == 0 || MODE == 2) {
            const size_t lda = (MODE == 0) ? (size_t)Cdim : (size_t)Ndim;
            const int ar = tid >> 3, ac = (tid & 7) * 4;
#pragma unroll
            for (int it = 0; it < 4; it++)
                r[it] = *(const float4*)(Ap + (size_t)(bm + ar + 32*it) * lda + k0 + ac);
        } else {
            const int kr = tid >> 5, mc = (tid & 31) * 4;
#pragma unroll
            for (int it = 0; it < 4; it++)
                r[it] = *(const float4*)(Ap + (size_t)(k0 + kr + 8*it) * Ndim + bm + mc);
        }
    };
    auto loadB = [&](int k0, float4* r) {
        if (MODE == 0 || MODE == 1) {
            const int kr = tid >> 5, nc = (tid & 31) * 4;
#pragma unroll
            for (int it = 0; it < 4; it++)
                r[it] = *(const float4*)(Bp + (size_t)(k0 + kr + 8*it) * Ndim + bn + nc);
        } else {
            const int nr = tid >> 3, kc = (tid & 7) * 4;
#pragma unroll
            for (int it = 0; it < 4; it++)
                r[it] = *(const float4*)(Bp + (size_t)(bn + nr + 32*it) * HWdim + k0 + kc);
        }
    };
    auto storeA = [&](const float4* r) {
        if (MODE == 0 || MODE == 2) {
            const int ar = tid >> 3, ac = (tid & 7) * 4;
#pragma unroll
            for (int it = 0; it < 4; it++) {
                const float v[4] = {r[it].x, r[it].y, r[it].z, r[it].w};
                __nv_bfloat16 h[4], l[4];
#pragma unroll
                for (int j = 0; j < 4; j++) split_bf16(v[j], h[j], l[j]);
                int row = ar + 32*it;
                *(__nv_bfloat162*)&Ah[row][ac]     = __nv_bfloat162(h[0], h[1]);
                *(__nv_bfloat162*)&Ah[row][ac + 2] = __nv_bfloat162(h[2], h[3]);
                *(__nv_bfloat162*)&Al[row][ac]     = __nv_bfloat162(l[0], l[1]);
                *(__nv_bfloat162*)&Al[row][ac + 2] = __nv_bfloat162(l[2], l[3]);
            }
        } else {
            const int kr = tid >> 5, mc = (tid & 31) * 4;
#pragma unroll
            for (int it = 0; it < 4; it++) {
                const float v[4] = {r[it].x, r[it].y, r[it].z, r[it].w};
                int k = kr + 8*it;
#pragma unroll
                for (int j = 0; j < 4; j++) {
                    __nv_bfloat16 h, l;
                    split_bf16(v[j], h, l);
                    Ah[mc + j][k] = h;
                    Al[mc + j][k] = l;
                }
            }
        }
    };
    auto storeB = [&](const float4* r) {
        if (MODE == 0 || MODE == 1) {
            const int kr = tid >> 5, nc = (tid & 31) * 4;
#pragma unroll
            for (int it = 0; it < 4; it++) {
                const float v[4] = {r[it].x, r[it].y, r[it].z, r[it].w};
                __nv_bfloat16 h[4], l[4];
#pragma unroll
                for (int j = 0; j < 4; j++) split_bf16(v[j], h[j], l[j]);
                int k = kr + 8*it;
                *(__nv_bfloat162*)&Bh[k][nc]     = __nv_bfloat162(h[0], h[1]);
                *(__nv_bfloat162*)&Bh[k][nc + 2] = __nv_bfloat162(h[2], h[3]);
                *(__nv_bfloat162*)&Bl[k][nc]     = __nv_bfloat162(l[0], l[1]);
                *(__nv_bfloat162*)&Bl[k][nc + 2] = __nv_bfloat162(l[2], l[3]);
            }
        } else {
            const int nr = tid >> 3, kc = (tid & 7) * 4;
#pragma unroll
            for (int it = 0; it < 4; it++) {
                const float v[4] = {r[it].x, r[it].y, r[it].z, r[it].w};
                int n = nr + 32*it;
#pragma unroll
                for (int j = 0; j < 4; j++) {
                    __nv_bfloat16 h, l;
                    split_bf16(v[j], h, l);
                    Bh[kc + j][n] = h;
                    Bl[kc + j][n] = l;
                }
            }
        }
    };

    float acc[4][4][4] = {};

    loadA(0, pa);
    loadB(0, pb);

    for (int s = 0; s < NSTG; s++) {
        storeA(pa);
        storeB(pb);
        __syncthreads();
        if (s + 1 < NSTG) {
            loadA((s + 1) * 32, pa);
            loadB((s + 1) * 32, pb);
        }
#pragma unroll
        for (int k16 = 0; k16 < 32; k16 += 16) {
            uint32_t a[4][4], b_hi[4][2], b_lo[4][2];
#pragma unroll
            for (int mi = 0; mi < 4; mi++) {
                uint32_t ad = smem_u32(&Ah[wm + mi*16 + (lane & 15)][k16 + ((lane >> 4) << 3)]);
                LDMX4(a[mi][0], a[mi][1], a[mi][2], a[mi][3], ad);
            }
#pragma unroll
            for (int ni = 0; ni < 4; ni++) {
                uint32_t bd  = smem_u32(&Bh[k16 + (lane & 15)][wn + ni*8]);
                LDMX2T(b_hi[ni][0], b_hi[ni][1], bd);
                uint32_t bd2 = smem_u32(&Bl[k16 + (lane & 15)][wn + ni*8]);
                LDMX2T(b_lo[ni][0], b_lo[ni][1], bd2);
            }
            // hi*hi and hi*lo
#pragma unroll
            for (int mi = 0; mi < 4; mi++)
#pragma unroll
                for (int ni = 0; ni < 4; ni++) {
                    MMA_B16(acc[mi][ni][0], acc[mi][ni][1], acc[mi][ni][2], acc[mi][ni][3],
                            a[mi][0], a[mi][1], a[mi][2], a[mi][3],
                            b_hi[ni][0], b_hi[ni][1]);
                    MMA_B16(acc[mi][ni][0], acc[mi][ni][1], acc[mi][ni][2], acc[mi][ni][3],
                            a[mi][0], a[mi][1], a[mi][2], a[mi][3],
                            b_lo[ni][0], b_lo[ni][1]);
                }
            // lo*hi
#pragma unroll
            for (int mi = 0; mi < 4; mi++) {
                uint32_t ad = smem_u32(&Al[wm + mi*16 + (lane & 15)][k16 + ((lane >> 4) << 3)]);
                LDMX4(a[mi][0], a[mi][1], a[mi][2], a[mi][3], ad);
            }
#pragma unroll
            for (int mi = 0; mi < 4; mi++)
#pragma unroll
                for (int ni = 0; ni < 4; ni++)
                    MMA_B16(acc[mi][ni][0], acc[mi][ni][1], acc[mi][ni][2], acc[mi][ni][3],
                            a[mi][0], a[mi][1], a[mi][2], a[mi][3],
                            b_hi[ni][0], b_hi[ni][1]);
        }
        __syncthreads();
    }

    // ---- epilogue ----
    const size_t ldc = (MODE == 1) ? (size_t)HWdim : (size_t)Ndim;
    const int r = lane >> 2, cc = (lane & 3) * 2;
#pragma unroll
    for (int mi = 0; mi < 4; mi++) {
        const int row0 = bm + wm + mi*16 + r;
        const int row1 = row0 + 8;
        float bi0 = 0.f, bi1 = 0.f;
        if (MODE == 0) { bi0 = bias[row0]; bi1 = bias[row1]; }
#pragma unroll
        for (int ni = 0; ni < 4; ni++) {
            const int col = bn + wn + ni*8 + cc;
            float2 v0 = make_float2(acc[mi][ni][0], acc[mi][ni][1]);
            float2 v1 = make_float2(acc[mi][ni][2], acc[mi][ni][3]);
            if (MODE == 0) {
                v0.x += bi0; v0.y += bi0;
                v1.x += bi1; v1.y += bi1;
                if (resid) {
                    float2 r0 = *(const float2*)(resid + (size_t)row0 * ldc + col);
                    float2 r1 = *(const float2*)(resid + (size_t)row1 * ldc + col);
                    v0.x += r0.x; v0.y += r0.y;
                    v1.x += r1.x; v1.y += r1.y;
                }
            } else if (MODE == 1) {
                v0.x *= SCALEv; v0.y *= SCALEv;
                v1.x *= SCALEv; v1.y *= SCALEv;
            }
            *(float2*)(Cp + (size_t)row0 * ldc + col) = v0;
            *(float2*)(Cp + (size_t)row1 * ldc + col) = v1;
        }
    }
}

// ---------------- row softmax over 2304 cols ----------------
__global__ void __launch_bounds__(256)
softmax_kernel() {
    float* row = g_s + (size_t)blockIdx.x * HWdim;
    const int tid = threadIdx.x;
    float r[9];
    float mx = -1e30f;
#pragma unroll
    for (int i = 0; i < 9; i++) {
        r[i] = row[tid + i * 256];
        mx = fmaxf(mx, r[i]);
    }
    __shared__ float sh[256];
    sh[tid] = mx;
    __syncthreads();
    for (int off = 128; off > 0; off >>= 1) {
        if (tid < off) sh[tid] = fmaxf(sh[tid], sh[tid + off]);
        __syncthreads();
    }
    mx = sh[0];
    __syncthreads();
    float s = 0.f;
#pragma unroll
    for (int i = 0; i < 9; i++) {
        r[i] = __expf(r[i] - mx);
        s += r[i];
    }
    sh[tid] = s;
    __syncthreads();
    for (int off = 128; off > 0; off >>= 1) {
        if (tid < off) sh[tid] += sh[tid + off];
        __syncthreads();
    }
    const float inv = 1.f / sh[0];
#pragma unroll
    for (int i = 0; i < 9; i++) row[tid + i * 256] = r[i] * inv;
}

// ---------------- launch ----------------
extern "C" void kernel_launch(void* const* d_in, const int* in_sizes, int n_in,
                              void* d_out, int out_size) {
    float *p_hn, *p_q, *p_k, *p_v, *p_of, *p_s;
    cudaGetSymbolAddress((void**)&p_hn, g_hn);
    cudaGetSymbolAddress((void**)&p_q,  g_q);
    cudaGetSymbolAddress((void**)&p_k,  g_k);
    cudaGetSymbolAddress((void**)&p_v,  g_v);
    cudaGetSymbolAddress((void**)&p_of, g_of);
    cudaGetSymbolAddress((void**)&p_s,  g_s);

    const float* x     = (const float*)d_in[0];
    const float* gamma = (const float*)d_in[1];
    const float* beta  = (const float*)d_in[2];
    const float* wq    = (const float*)d_in[3];
    const float* bq    = (const float*)d_in[4];
    const float* wk    = (const float*)d_in[5];
    const float* bk    = (const float*)d_in[6];
    const float* wv    = (const float*)d_in[7];
    const float* bv    = (const float*)d_in[8];
    const float* wo    = (const float*)d_in[9];
    const float* bo    = (const float*)d_in[10];
    float* out = (float*)d_out;

    // 1. GroupNorm
    gn_stats_kernel<<<Gdim, 1024>>>(x);
    gn_apply_kernel<<<(Cdim * Ndim / 4) / 256, 256>>>(x, gamma, beta);

    // 2. Q/K/V projections
    dim3 gProj(Ndim / 128, Cdim / 128);          // (144, 4)
    mma_gemm<0><<<gProj, 256>>>(wq, p_hn, bq, (const float*)0, p_q);
    mma_gemm<0><<<gProj, 256>>>(wk, p_hn, bk, (const float*)0, p_k);
    mma_gemm<0><<<gProj, 256>>>(wv, p_hn, bv, (const float*)0, p_v);

    // 3. scores = scale * Q^T K per frame
    dim3 gSc(HWdim / 128, HWdim / 128, Tdim);    // (18, 18, 8)
    mma_gemm<1><<<gSc, 256>>>(p_q, p_k, (const float*)0, (const float*)0, p_s);

    // 4. softmax
    softmax_kernel<<<Tdim * HWdim, 256>>>();

    // 5. O = V @ P^T per frame
    dim3 gPV(HWdim / 128, Cdim / 128, Tdim);     // (18, 4, 8)
    mma_gemm<2><<<gPV, 256>>>(p_v, p_s, (const float*)0, (const float*)0, p_of);

    // 6. output projection + bias + residual
    mma_gemm<0><<<gProj, 256>>>(wo, p_of, bo, x, out);
}

// round 6
// speedup vs baseline: 2.3651x; 1.4798x over previous
#include <cuda_runtime.h>
#include <cuda_bf16.h>
#include <stdint.h>
#include <math.h>

#define Cdim   512
#define Tdim   8
#define HWdim  2304
#define Ndim   18432
#define Gdim   32
#define CPG    16
#define EPSv   1e-6f
#define SCALEv 0.044194173824159216f
#define CN     ((size_t)Cdim * Ndim)
#define SSZ    ((size_t)Tdim * HWdim * HWdim)

// ---------------- scratch ----------------
__device__ float g_mean[Gdim];
__device__ float g_rstd[Gdim];
__device__ float g_s[SSZ];
__device__ __nv_bfloat16 g_hnh[CN], g_hnl[CN];
__device__ __nv_bfloat16 g_qh [CN], g_ql [CN];
__device__ __nv_bfloat16 g_kh [CN], g_kl [CN];
__device__ __nv_bfloat16 g_vh [CN], g_vl [CN];
__device__ __nv_bfloat16 g_ofh[CN], g_ofl[CN];
__device__ __nv_bfloat16 g_ph [SSZ], g_pl [SSZ];
__device__ __nv_bfloat16 g_wh[4 * Cdim * Cdim], g_wl[4 * Cdim * Cdim];

__device__ __forceinline__ void split_bf16(float x, __nv_bfloat16& h, __nv_bfloat16& l) {
    h = __float2bfloat16(x);
    l = __float2bfloat16(x - __bfloat162float(h));
}

// ---------------- weight split ----------------
__global__ void splitw_kernel(const float* __restrict__ w,
                              __nv_bfloat16* __restrict__ oh,
                              __nv_bfloat16* __restrict__ ol) {
    int i = (blockIdx.x * 256 + threadIdx.x) * 4;
    float4 v = *(const float4*)(w + i);
    __nv_bfloat16 h[4], l[4];
    split_bf16(v.x, h[0], l[0]); split_bf16(v.y, h[1], l[1]);
    split_bf16(v.z, h[2], l[2]); split_bf16(v.w, h[3], l[3]);
    *(__nv_bfloat162*)(oh + i)     = __nv_bfloat162(h[0], h[1]);
    *(__nv_bfloat162*)(oh + i + 2) = __nv_bfloat162(h[2], h[3]);
    *(__nv_bfloat162*)(ol + i)     = __nv_bfloat162(l[0], l[1]);
    *(__nv_bfloat162*)(ol + i + 2) = __nv_bfloat162(l[2], l[3]);
}

// ---------------- GroupNorm ----------------
__global__ void gn_stats_kernel(const float* __restrict__ x) {
    const int g = blockIdx.x;
    const float4* base = (const float4*)(x + (size_t)g * CPG * Ndim);
    const int n4 = (CPG * Ndim) / 4;
    float s = 0.f, ss = 0.f;
    for (int i = threadIdx.x; i < n4; i += blockDim.x) {
        float4 v = base[i];
        s  += v.x + v.y + v.z + v.w;
        ss += v.x*v.x + v.y*v.y + v.z*v.z + v.w*v.w;
    }
    __shared__ float sh1[1024];
    __shared__ float sh2[1024];
    sh1[threadIdx.x] = s; sh2[threadIdx.x] = ss;
    __syncthreads();
    for (int off = 512; off > 0; off >>= 1) {
        if (threadIdx.x < off) {
            sh1[threadIdx.x] += sh1[threadIdx.x + off];
            sh2[threadIdx.x] += sh2[threadIdx.x + off];
        }
        __syncthreads();
    }
    if (threadIdx.x == 0) {
        const float inv = 1.f / (float)(CPG * Ndim);
        float m = sh1[0] * inv;
        float var = sh2[0] * inv - m * m;
        g_mean[g] = m;
        g_rstd[g] = rsqrtf(var + EPSv);
    }
}

__global__ void gn_apply_kernel(const float* __restrict__ x,
                                const float* __restrict__ gamma,
                                const float* __restrict__ beta) {
    int i4 = blockIdx.x * blockDim.x + threadIdx.x;
    int c  = (i4 * 4) / Ndim;
    int g  = c >> 4;
    float r  = g_rstd[g];
    float ga = gamma[c] * r;
    float be = beta[c] - g_mean[g] * ga;
    float4 v = ((const float4*)x)[i4];
    float o[4] = {v.x*ga+be, v.y*ga+be, v.z*ga+be, v.w*ga+be};
    __nv_bfloat16 h[4], l[4];
#pragma unroll
    for (int j = 0; j < 4; j++) split_bf16(o[j], h[j], l[j]);
    size_t i = (size_t)i4 * 4;
    *(__nv_bfloat162*)(g_hnh + i)     = __nv_bfloat162(h[0], h[1]);
    *(__nv_bfloat162*)(g_hnh + i + 2) = __nv_bfloat162(h[2], h[3]);
    *(__nv_bfloat162*)(g_hnl + i)     = __nv_bfloat162(l[0], l[1]);
    *(__nv_bfloat162*)(g_hnl + i + 2) = __nv_bfloat162(l[2], l[3]);
}

// ---------------- PTX helpers ----------------
__device__ __forceinline__ uint32_t smem_u32(const void* p) {
    return (uint32_t)__cvta_generic_to_shared(p);
}
#define CP16(d,s) asm volatile("cp.async.cg.shared.global [%0], [%1], 16;" :: "r"(d), "l"(s))
#define CPCOMMIT() asm volatile("cp.async.commit_group;")
#define CPWAIT(n)  asm volatile("cp.async.wait_group %0;" :: "n"(n) : "memory")

#define LDMX4(r0,r1,r2,r3,addr) \
    asm volatile("ldmatrix.sync.aligned.m8n8.x4.shared.b16 {%0,%1,%2,%3}, [%4];" \
        : "=r"(r0),"=r"(r1),"=r"(r2),"=r"(r3) : "r"(addr))
#define LDMX4T(r0,r1,r2,r3,addr) \
    asm volatile("ldmatrix.sync.aligned.m8n8.x4.trans.shared.b16 {%0,%1,%2,%3}, [%4];" \
        : "=r"(r0),"=r"(r1),"=r"(r2),"=r"(r3) : "r"(addr))
#define LDMX2(r0,r1,addr) \
    asm volatile("ldmatrix.sync.aligned.m8n8.x2.shared.b16 {%0,%1}, [%2];" \
        : "=r"(r0),"=r"(r1) : "r"(addr))
#define LDMX2T(r0,r1,addr) \
    asm volatile("ldmatrix.sync.aligned.m8n8.x2.trans.shared.b16 {%0,%1}, [%2];" \
        : "=r"(r0),"=r"(r1) : "r"(addr))
#define MMA_B16(c0,c1,c2,c3,a0,a1,a2,a3,b0,b1) \
    asm volatile("mma.sync.aligned.m16n8k16.row.col.f32.bf16.bf16.f32 " \
        "{%0,%1,%2,%3}, {%4,%5,%6,%7}, {%8,%9}, {%0,%1,%2,%3};" \
        : "+f"(c0),"+f"(c1),"+f"(c2),"+f"(c3) \
        : "r"(a0),"r"(a1),"r"(a2),"r"(a3),"r"(b0),"r"(b1))

// Stage layout (halves): A_h[5120] A_l[5120] B_h[5120] B_l[5120]; 2 stages.
#define STG_H 20480
#define SMEMB (2 * STG_H * 2)   // bytes = 81920

// MODE 0: proj   A=weights hi/lo [512][512], B=[512][Ndim]           -> split out or fp32(+bias+resid)
// MODE 1: scores A=q hi/lo [k][m] str Ndim,  B=k hi/lo [k][n] str Ndim -> fp32 S * scale
// MODE 2: pv     A=v hi/lo [m][k] str Ndim,  B=P hi/lo [n][k] str HWdim -> split of
template<int MODE, bool SPLIT>
__global__ void __launch_bounds__(256)
mma_gemm(const __nv_bfloat16* __restrict__ Agh, const __nv_bfloat16* __restrict__ Agl,
         const __nv_bfloat16* __restrict__ Bgh, const __nv_bfloat16* __restrict__ Bgl,
         const float* __restrict__ bias, const float* __restrict__ resid,
         float* __restrict__ Cf, __nv_bfloat16* __restrict__ Ch, __nv_bfloat16* __restrict__ Cl)
{
    constexpr int KDIM = (MODE == 2) ? HWdim : Cdim;
    constexpr int NSTG = KDIM / 32;

    extern __shared__ __nv_bfloat16 sm[];

    const int tid  = threadIdx.x;
    const int lane = tid & 31;
    const int warp = tid >> 5;
    const int wm   = (warp >> 2) * 64;
    const int wn   = (warp & 3) * 32;
    const int bn   = blockIdx.x * 128;
    const int bm   = blockIdx.y * 128;
    const int f    = (MODE == 0) ? 0 : blockIdx.z;

    const __nv_bfloat16 *Aph, *Apl, *Bph, *Bpl;
    if (MODE == 0)      { Aph = Agh; Apl = Agl; Bph = Bgh; Bpl = Bgl; }
    else if (MODE == 1) { Aph = Agh + (size_t)f * HWdim; Apl = Agl + (size_t)f * HWdim;
                          Bph = Bgh + (size_t)f * HWdim; Bpl = Bgl + (size_t)f * HWdim; }
    else                { Aph = Agh + (size_t)f * HWdim; Apl = Agl + (size_t)f * HWdim;
                          Bph = Bgh + (size_t)f * HWdim * HWdim; Bpl = Bgl + (size_t)f * HWdim * HWdim; }

    auto issue = [&](int buf, int k0) {
        __nv_bfloat16* Sa_h = sm + buf * STG_H;
        __nv_bfloat16* Sa_l = Sa_h + 5120;
        __nv_bfloat16* Sb_h = Sa_h + 10240;
        __nv_bfloat16* Sb_l = Sa_h + 15360;
        // ---- A ----
        if (MODE == 1) {                       // [k][m] -> [32][136]
            int row = tid >> 3, c0 = (tid & 7) * 8;
            const __nv_bfloat16* s0 = Aph + (size_t)(k0 + row) * Ndim + bm;
            const __nv_bfloat16* s1 = Apl + (size_t)(k0 + row) * Ndim + bm;
            CP16(smem_u32(Sa_h + row*136 + c0),      s0 + c0);
            CP16(smem_u32(Sa_h + row*136 + c0 + 64), s0 + c0 + 64);
            CP16(smem_u32(Sa_l + row*136 + c0),      s1 + c0);
            CP16(smem_u32(Sa_l + row*136 + c0 + 64), s1 + c0 + 64);
        } else {                               // [m][k] -> [128][40]
            const size_t lda = (MODE == 0) ? (size_t)Cdim : (size_t)Ndim;
            int row = tid >> 1, c0 = (tid & 1) * 8;
            const __nv_bfloat16* s0 = Aph + (size_t)(bm + row) * lda + k0;
            const __nv_bfloat16* s1 = Apl + (size_t)(bm + row) * lda + k0;
            CP16(smem_u32(Sa_h + row*40 + c0),      s0 + c0);
            CP16(smem_u32(Sa_h + row*40 + c0 + 16), s0 + c0 + 16);
            CP16(smem_u32(Sa_l + row*40 + c0),      s1 + c0);
            CP16(smem_u32(Sa_l + row*40 + c0 + 16), s1 + c0 + 16);
        }
        // ---- B ----
        if (MODE == 2) {                       // [n][k] -> [128][40]
            int row = tid >> 1, c0 = (tid & 1) * 8;
            const __nv_bfloat16* s0 = Bph + (size_t)(bn + row) * HWdim + k0;
            const __nv_bfloat16* s1 = Bpl + (size_t)(bn + row) * HWdim + k0;
            CP16(smem_u32(Sb_h + row*40 + c0),      s0 + c0);
            CP16(smem_u32(Sb_h + row*40 + c0 + 16), s0 + c0 + 16);
            CP16(smem_u32(Sb_l + row*40 + c0),      s1 + c0);
            CP16(smem_u32(Sb_l + row*40 + c0 + 16), s1 + c0 + 16);
        } else {                               // [k][n] -> [32][136]
            int row = tid >> 3, c0 = (tid & 7) * 8;
            const __nv_bfloat16* s0 = Bph + (size_t)(k0 + row) * Ndim + bn;
            const __nv_bfloat16* s1 = Bpl + (size_t)(k0 + row) * Ndim + bn;
            CP16(smem_u32(Sb_h + row*136 + c0),      s0 + c0);
            CP16(smem_u32(Sb_h + row*136 + c0 + 64), s0 + c0 + 64);
            CP16(smem_u32(Sb_l + row*136 + c0),      s1 + c0);
            CP16(smem_u32(Sb_l + row*136 + c0 + 64), s1 + c0 + 64);
        }
    };

    float acc[4][4][4] = {};

    issue(0, 0); CPCOMMIT();

    for (int s = 0; s < NSTG; s++) {
        if (s + 1 < NSTG) { issue((s + 1) & 1, (s + 1) * 32); CPCOMMIT(); CPWAIT(1); }
        else CPWAIT(0);
        __syncthreads();

        const __nv_bfloat16* Sa_h = sm + (s & 1) * STG_H;
        const __nv_bfloat16* Sa_l = Sa_h + 5120;
        const __nv_bfloat16* Sb_h = Sa_h + 10240;
        const __nv_bfloat16* Sb_l = Sa_h + 15360;

#pragma unroll
        for (int k16 = 0; k16 < 32; k16 += 16) {
            uint32_t a[4][4], bh[4][2], bl[4][2];
            // A hi fragments
#pragma unroll
            for (int mi = 0; mi < 4; mi++) {
                if (MODE == 1) {
                    int row = k16 + (lane & 7) + ((lane >> 4) << 3);
                    int col = wm + mi*16 + (((lane >> 3) & 1) << 3);
                    LDMX4T(a[mi][0], a[mi][1], a[mi][2], a[mi][3],
                           smem_u32(Sa_h + row*136 + col));
                } else {
                    LDMX4(a[mi][0], a[mi][1], a[mi][2], a[mi][3],
                          smem_u32(Sa_h + (wm + mi*16 + (lane & 15))*40 + k16 + ((lane >> 4) << 3)));
                }
            }
            // B hi/lo fragments
#pragma unroll
            for (int ni = 0; ni < 4; ni++) {
                if (MODE == 2) {
                    uint32_t ad = smem_u32(Sb_h + (wn + ni*8 + (lane & 7))*40 + k16 + (((lane >> 3) & 1) << 3));
                    LDMX2(bh[ni][0], bh[ni][1], ad);
                    uint32_t ad2 = smem_u32(Sb_l + (wn + ni*8 + (lane & 7))*40 + k16 + (((lane >> 3) & 1) << 3));
                    LDMX2(bl[ni][0], bl[ni][1], ad2);
                } else {
                    uint32_t ad = smem_u32(Sb_h + (k16 + (lane & 15))*136 + wn + ni*8);
                    LDMX2T(bh[ni][0], bh[ni][1], ad);
                    uint32_t ad2 = smem_u32(Sb_l + (k16 + (lane & 15))*136 + wn + ni*8);
                    LDMX2T(bl[ni][0], bl[ni][1], ad2);
                }
            }
            // hi*hi + hi*lo
#pragma unroll
            for (int mi = 0; mi < 4; mi++)
#pragma unroll
                for (int ni = 0; ni < 4; ni++) {
                    MMA_B16(acc[mi][ni][0], acc[mi][ni][1], acc[mi][ni][2], acc[mi][ni][3],
                            a[mi][0], a[mi][1], a[mi][2], a[mi][3], bh[ni][0], bh[ni][1]);
                    MMA_B16(acc[mi][ni][0], acc[mi][ni][1], acc[mi][ni][2], acc[mi][ni][3],
                            a[mi][0], a[mi][1], a[mi][2], a[mi][3], bl[ni][0], bl[ni][1]);
                }
            // A lo fragments, lo*hi
#pragma unroll
            for (int mi = 0; mi < 4; mi++) {
                if (MODE == 1) {
                    int row = k16 + (lane & 7) + ((lane >> 4) << 3);
                    int col = wm + mi*16 + (((lane >> 3) & 1) << 3);
                    LDMX4T(a[mi][0], a[mi][1], a[mi][2], a[mi][3],
                           smem_u32(Sa_l + row*136 + col));
                } else {
                    LDMX4(a[mi][0], a[mi][1], a[mi][2], a[mi][3],
                          smem_u32(Sa_l + (wm + mi*16 + (lane & 15))*40 + k16 + ((lane >> 4) << 3)));
                }
            }
#pragma unroll
            for (int mi = 0; mi < 4; mi++)
#pragma unroll
                for (int ni = 0; ni < 4; ni++)
                    MMA_B16(acc[mi][ni][0], acc[mi][ni][1], acc[mi][ni][2], acc[mi][ni][3],
                            a[mi][0], a[mi][1], a[mi][2], a[mi][3], bh[ni][0], bh[ni][1]);
        }
        __syncthreads();
    }

    // ---- epilogue ----
    const size_t ldc = (MODE == 1) ? (size_t)HWdim : (size_t)Ndim;
    float* Cpf = 0; __nv_bfloat16 *Cph = 0, *Cpl = 0;
    if (MODE == 1)      Cpf = Cf + (size_t)f * HWdim * HWdim;
    else if (MODE == 2) { Cph = Ch + (size_t)f * HWdim; Cpl = Cl + (size_t)f * HWdim; }
    else if (SPLIT)     { Cph = Ch; Cpl = Cl; }
    else                Cpf = Cf;

    const int r = lane >> 2, cc = (lane & 3) * 2;
#pragma unroll
    for (int mi = 0; mi < 4; mi++) {
        const int row0 = bm + wm + mi*16 + r;
        const int row1 = row0 + 8;
        float bi0 = 0.f, bi1 = 0.f;
        if (MODE == 0) { bi0 = bias[row0]; bi1 = bias[row1]; }
#pragma unroll
        for (int ni = 0; ni < 4; ni++) {
            const int col = bn + wn + ni*8 + cc;
            float v00 = acc[mi][ni][0], v01 = acc[mi][ni][1];
            float v10 = acc[mi][ni][2], v11 = acc[mi][ni][3];
            if (MODE == 0) { v00 += bi0; v01 += bi0; v10 += bi1; v11 += bi1; }
            if (MODE == 1) { v00 *= SCALEv; v01 *= SCALEv; v10 *= SCALEv; v11 *= SCALEv; }
            if (SPLIT) {
                __nv_bfloat16 h0,l0,h1,l1,h2,l2,h3,l3;
                split_bf16(v00,h0,l0); split_bf16(v01,h1,l1);
                split_bf16(v10,h2,l2); split_bf16(v11,h3,l3);
                *(__nv_bfloat162*)(Cph + (size_t)row0*ldc + col) = __nv_bfloat162(h0,h1);
                *(__nv_bfloat162*)(Cpl + (size_t)row0*ldc + col) = __nv_bfloat162(l0,l1);
                *(__nv_bfloat162*)(Cph + (size_t)row1*ldc + col) = __nv_bfloat162(h2,h3);
                *(__nv_bfloat162*)(Cpl + (size_t)row1*ldc + col) = __nv_bfloat162(l2,l3);
            } else {
                if (MODE == 0 && resid) {
                    float2 r0 = *(const float2*)(resid + (size_t)row0*ldc + col);
                    float2 r1 = *(const float2*)(resid + (size_t)row1*ldc + col);
                    v00 += r0.x; v01 += r0.y; v10 += r1.x; v11 += r1.y;
                }
                *(float2*)(Cpf + (size_t)row0*ldc + col) = make_float2(v00, v01);
                *(float2*)(Cpf + (size_t)row1*ldc + col) = make_float2(v10, v11);
            }
        }
    }
}

// ---------------- softmax: fp32 scores -> bf16 hi/lo probs ----------------
__global__ void __launch_bounds__(256)
softmax_kernel() {
    const size_t base = (size_t)blockIdx.x * HWdim;
    const float* row = g_s + base;
    const int tid = threadIdx.x;
    float r[9];
    float mx = -1e30f;
#pragma unroll
    for (int i = 0; i < 9; i++) {
        r[i] = row[tid + i * 256];
        mx = fmaxf(mx, r[i]);
    }
    __shared__ float sh[256];
    sh[tid] = mx;
    __syncthreads();
    for (int off = 128; off > 0; off >>= 1) {
        if (tid < off) sh[tid] = fmaxf(sh[tid], sh[tid + off]);
        __syncthreads();
    }
    mx = sh[0];
    __syncthreads();
    float s = 0.f;
#pragma unroll
    for (int i = 0; i < 9; i++) {
        r[i] = __expf(r[i] - mx);
        s += r[i];
    }
    sh[tid] = s;
    __syncthreads();
    for (int off = 128; off > 0; off >>= 1) {
        if (tid < off) sh[tid] += sh[tid + off];
        __syncthreads();
    }
    const float inv = 1.f / sh[0];
#pragma unroll
    for (int i = 0; i < 9; i++) {
        float p = r[i] * inv;
        __nv_bfloat16 h, l;
        split_bf16(p, h, l);
        g_ph[base + tid + i * 256] = h;
        g_pl[base + tid + i * 256] = l;
    }
}

// ---------------- launch ----------------
extern "C" void kernel_launch(void* const* d_in, const int* in_sizes, int n_in,
                              void* d_out, int out_size) {
    __nv_bfloat16 *p_hnh, *p_hnl, *p_qh, *p_ql, *p_kh, *p_kl, *p_vh, *p_vl, *p_ofh, *p_ofl, *p_ph, *p_pl, *p_wh, *p_wl;
    float* p_s;
    cudaGetSymbolAddress((void**)&p_hnh, g_hnh); cudaGetSymbolAddress((void**)&p_hnl, g_hnl);
    cudaGetSymbolAddress((void**)&p_qh,  g_qh);  cudaGetSymbolAddress((void**)&p_ql,  g_ql);
    cudaGetSymbolAddress((void**)&p_kh,  g_kh);  cudaGetSymbolAddress((void**)&p_kl,  g_kl);
    cudaGetSymbolAddress((void**)&p_vh,  g_vh);  cudaGetSymbolAddress((void**)&p_vl,  g_vl);
    cudaGetSymbolAddress((void**)&p_ofh, g_ofh); cudaGetSymbolAddress((void**)&p_ofl, g_ofl);
    cudaGetSymbolAddress((void**)&p_ph,  g_ph);  cudaGetSymbolAddress((void**)&p_pl,  g_pl);
    cudaGetSymbolAddress((void**)&p_wh,  g_wh);  cudaGetSymbolAddress((void**)&p_wl,  g_wl);
    cudaGetSymbolAddress((void**)&p_s,   g_s);

    static bool attr_done = false;
    if (!attr_done) {
        cudaFuncSetAttribute(mma_gemm<0,true >, cudaFuncAttributeMaxDynamicSharedMemorySize, SMEMB);
        cudaFuncSetAttribute(mma_gemm<0,false>, cudaFuncAttributeMaxDynamicSharedMemorySize, SMEMB);
        cudaFuncSetAttribute(mma_gemm<1,false>, cudaFuncAttributeMaxDynamicSharedMemorySize, SMEMB);
        cudaFuncSetAttribute(mma_gemm<2,true >, cudaFuncAttributeMaxDynamicSharedMemorySize, SMEMB);
        attr_done = true;
    }

    const float* x     = (const float*)d_in[0];
    const float* gamma = (const float*)d_in[1];
    const float* beta  = (const float*)d_in[2];
    const float* wq    = (const float*)d_in[3];
    const float* bq    = (const float*)d_in[4];
    const float* wk    = (const float*)d_in[5];
    const float* bk    = (const float*)d_in[6];
    const float* wv    = (const float*)d_in[7];
    const float* bv    = (const float*)d_in[8];
    const float* wo    = (const float*)d_in[9];
    const float* bo    = (const float*)d_in[10];
    float* out = (float*)d_out;

    const int WSZ = Cdim * Cdim;

    // 0. split weights
    splitw_kernel<<<WSZ/1024, 256>>>(wq, p_wh + 0*WSZ, p_wl + 0*WSZ);
    splitw_kernel<<<WSZ/1024, 256>>>(wk, p_wh + 1*WSZ, p_wl + 1*WSZ);
    splitw_kernel<<<WSZ/1024, 256>>>(wv, p_wh + 2*WSZ, p_wl + 2*WSZ);
    splitw_kernel<<<WSZ/1024, 256>>>(wo, p_wh + 3*WSZ, p_wl + 3*WSZ);

    // 1. GroupNorm -> split hn
    gn_stats_kernel<<<Gdim, 1024>>>(x);
    gn_apply_kernel<<<(int)(CN / 4) / 256, 256>>>(x, gamma, beta);

    // 2. Q/K/V projections (split outputs)
    dim3 gProj(Ndim / 128, Cdim / 128);
    mma_gemm<0,true><<<gProj, 256, SMEMB>>>(p_wh + 0*WSZ, p_wl + 0*WSZ, p_hnh, p_hnl, bq, 0, 0, p_qh, p_ql);
    mma_gemm<0,true><<<gProj, 256, SMEMB>>>(p_wh + 1*WSZ, p_wl + 1*WSZ, p_hnh, p_hnl, bk, 0, 0, p_kh, p_kl);
    mma_gemm<0,true><<<gProj, 256, SMEMB>>>(p_wh + 2*WSZ, p_wl + 2*WSZ, p_hnh, p_hnl, bv, 0, 0, p_vh, p_vl);

    // 3. scores
    dim3 gSc(HWdim / 128, HWdim / 128, Tdim);
    mma_gemm<1,false><<<gSc, 256, SMEMB>>>(p_qh, p_ql, p_kh, p_kl, 0, 0, p_s, 0, 0);

    // 4. softmax -> split probs
    softmax_kernel<<<Tdim * HWdim, 256>>>();

    // 5. PV (split of)
    dim3 gPV(HWdim / 128, Cdim / 128, Tdim);
    mma_gemm<2,true><<<gPV, 256, SMEMB>>>(p_vh, p_vl, p_ph, p_pl, 0, 0, 0, p_ofh, p_ofl);

    // 6. output projection + bias + residual
    mma_gemm<0,false><<<gProj, 256, SMEMB>>>(p_wh + 3*WSZ, p_wl + 3*WSZ, p_ofh, p_ofl, bo, x, out, 0, 0);
}